// round 2
// baseline (speedup 1.0000x reference)
#include <cuda_runtime.h>
#include <cstdint>

// Problem constants (fixed by the dataset): C=64 in-channels, T=8 terms, F=64 out.
#define C_DIM 64
#define T_DIM 8
#define F_DIM 64
#define TC_DIM 512  // T*C

#define EMAX 800000
#define NOUTMAX 50176  // 50000 rounded up to multiple of 128

typedef unsigned long long ull;

// ---------------- scratch (__device__ globals; no allocations allowed) ----------
__device__ int   g_is64;
__device__ int   g_count[NOUTMAX];
__device__ int   g_scan[NOUTMAX];
__device__ int   g_offsets[NOUTMAX + 1];
__device__ int   g_cursor[NOUTMAX];
__device__ int   g_bsum[64];
__device__ int   g_boff[64];
__device__ int   g_src[EMAX];                       // idx_in per CSR slot
__device__ float g_edgeW[(size_t)EMAX * T_DIM];     // 8 edge weights per CSR slot
__device__ float g_M[(size_t)NOUTMAX * TC_DIM];     // (N_OUT, 512) accumulator

// ---------------- index dtype helper --------------------------------------------
__device__ __forceinline__ int idx_at(const void* p, long long i) {
    if (g_is64) return (int)((const long long*)p)[i];
    return ((const int*)p)[i];
}

// ---------------- init: zero counters + detect int64 vs int32 indices -----------
__global__ void k_init(int nOut, const void* idx) {
    int i = blockIdx.x * blockDim.x + threadIdx.x;
    if (i < nOut) g_count[i] = 0;
    if (i == 0) {
        // int64 (nonneg < 2^31): every odd 32-bit word is zero.
        const unsigned* w = (const unsigned*)idx;
        int is64 = 1;
        for (int j = 0; j < 64; j++) {
            if (w[2 * j + 1] != 0u) { is64 = 0; break; }
        }
        g_is64 = is64;
    }
}

__global__ void k_hist(const void* idx, int E) {
    int e = blockIdx.x * blockDim.x + threadIdx.x;
    if (e < E) {
        int o = idx_at(idx, 2LL * e);
        atomicAdd(&g_count[o], 1);
    }
}

// ---------------- shuffle-based 3-pass scan --------------------------------------
__global__ void k_scan1(int nOut) {
    __shared__ int wsum[32];
    int tid = threadIdx.x;
    int lane = tid & 31, wid = tid >> 5;
    int i = blockIdx.x * 1024 + tid;
    int v = (i < nOut) ? g_count[i] : 0;

    int s = v;
#pragma unroll
    for (int off = 1; off < 32; off <<= 1) {
        int t = __shfl_up_sync(0xffffffffu, s, off);
        if (lane >= off) s += t;
    }
    if (lane == 31) wsum[wid] = s;
    __syncthreads();
    if (wid == 0) {
        int ws = wsum[lane];
#pragma unroll
        for (int off = 1; off < 32; off <<= 1) {
            int t = __shfl_up_sync(0xffffffffu, ws, off);
            if (lane >= off) ws += t;
        }
        wsum[lane] = ws;
    }
    __syncthreads();
    int incl = s + (wid > 0 ? wsum[wid - 1] : 0);
    if (i < nOut) g_scan[i] = incl;
    if (tid == 1023) g_bsum[blockIdx.x] = incl;
}

__global__ void k_scan2(int nb) {
    int lane = threadIdx.x & 31, wid = threadIdx.x >> 5;  // 64 threads, 2 warps
    __shared__ int w0sum;
    int v = (threadIdx.x < nb) ? g_bsum[threadIdx.x] : 0;
    int s = v;
#pragma unroll
    for (int off = 1; off < 32; off <<= 1) {
        int t = __shfl_up_sync(0xffffffffu, s, off);
        if (lane >= off) s += t;
    }
    if (wid == 0 && lane == 31) w0sum = s;
    __syncthreads();
    int incl = s + (wid == 1 ? w0sum : 0);
    g_boff[threadIdx.x] = incl - v;  // exclusive
}

__global__ void k_scan3(int nOut, int E) {
    int i = blockIdx.x * 1024 + threadIdx.x;
    if (i < nOut) {
        int off = g_boff[blockIdx.x] + g_scan[i] - g_count[i];
        g_offsets[i] = off;
        g_cursor[i]  = off;
    }
    if (blockIdx.x == 0 && threadIdx.x == 0) g_offsets[nOut] = E;
}

// Fill CSR: also pre-gather per-edge weight vector (transposed to (slot, T)).
__global__ void k_fill(const void* idx, const float* __restrict__ edge, int E) {
    int e = blockIdx.x * blockDim.x + threadIdx.x;
    if (e >= E) return;
    int o  = idx_at(idx, 2LL * e);
    int in = idx_at(idx, 2LL * e + 1);
    int p = atomicAdd(&g_cursor[o], 1);
    g_src[p] = in;
    float w[T_DIM];
#pragma unroll
    for (int t = 0; t < T_DIM; t++) w[t] = edge[(size_t)t * E + e];
    float4* dst = reinterpret_cast<float4*>(g_edgeW + (size_t)p * 8);
    dst[0] = make_float4(w[0], w[1], w[2], w[3]);
    dst[1] = make_float4(w[4], w[5], w[6], w[7]);
}

// ---------------- edge accumulation: M[o, t*64+c] -------------------------------
// 64 threads per output (one per channel c); f32x2 packed accumulators.
__global__ void k_accum(const float* __restrict__ node, int nOut) {
    int tid = threadIdx.x;
    int c = tid & 63;
    int o = blockIdx.x * 4 + (tid >> 6);
    if (o >= nOut) return;

    int beg = g_offsets[o];
    int end = g_offsets[o + 1];

    ull s0 = 0ull, s1 = 0ull, s2 = 0ull, s3 = 0ull;  // (0.f,0.f) packed

    for (int i = beg; i < end; i++) {
        int in = g_src[i];
        const ulonglong2* wp = reinterpret_cast<const ulonglong2*>(g_edgeW + (size_t)i * 8);
        ulonglong2 wA = wp[0];   // (w0,w1),(w2,w3)
        ulonglong2 wB = wp[1];   // (w4,w5),(w6,w7)
        float nv = __ldg(&node[(size_t)in * C_DIM + c]);
        ull nvd;
        asm("mov.b64 %0, {%1, %1};" : "=l"(nvd) : "r"(__float_as_uint(nv)));
        asm("fma.rn.f32x2 %0, %1, %2, %0;" : "+l"(s0) : "l"(wA.x), "l"(nvd));
        asm("fma.rn.f32x2 %0, %1, %2, %0;" : "+l"(s1) : "l"(wA.y), "l"(nvd));
        asm("fma.rn.f32x2 %0, %1, %2, %0;" : "+l"(s2) : "l"(wB.x), "l"(nvd));
        asm("fma.rn.f32x2 %0, %1, %2, %0;" : "+l"(s3) : "l"(wB.y), "l"(nvd));
    }

    size_t base = (size_t)o * TC_DIM + c;
    float2 f0 = *reinterpret_cast<float2*>(&s0);
    float2 f1 = *reinterpret_cast<float2*>(&s1);
    float2 f2 = *reinterpret_cast<float2*>(&s2);
    float2 f3 = *reinterpret_cast<float2*>(&s3);
    g_M[base + 0 * 64] = f0.x; g_M[base + 1 * 64] = f0.y;
    g_M[base + 2 * 64] = f1.x; g_M[base + 3 * 64] = f1.y;
    g_M[base + 4 * 64] = f2.x; g_M[base + 5 * 64] = f2.y;
    g_M[base + 6 * 64] = f3.x; g_M[base + 7 * 64] = f3.y;
}

// ---------------- GEMM: out = M(N_OUT x 512) @ Kflat(512 x 64) + bias -----------
// f32x2 packed: M-row pairs come packed from LDS.128; B tile stored duplicated.
#define BM 128
#define BN 64
#define BK 16
#define TM 8
#define TN 4

__global__ __launch_bounds__(256) void k_gemm(const float* __restrict__ Kf,
                                              const float* __restrict__ bias,
                                              float* __restrict__ out, int nOut) {
    __shared__ __align__(16) float Ms[BK][BM + 4];
    __shared__ __align__(16) ull   NsD[BK][BN];     // (b,b) duplicated pairs

    int tid = threadIdx.x;
    int tx = tid & 15;   // 16 column groups of 4
    int ty = tid >> 4;   // 16 row groups of 8
    int row0 = blockIdx.x * BM;

    ull acc2[TM / 2][TN];  // halves = (row 2p, row 2p+1), col j
#pragma unroll
    for (int p = 0; p < TM / 2; p++)
#pragma unroll
        for (int j = 0; j < TN; j++) acc2[p][j] = 0ull;

    for (int kb = 0; kb < TC_DIM; kb += BK) {
        // Load M tile: 128x16 = 512 float4, 2 per thread.
#pragma unroll
        for (int r = 0; r < 2; r++) {
            int idx = tid + r * 256;        // 0..511
            int m  = idx >> 2;              // 0..127
            int k4 = idx & 3;               // 0..3
            int row = row0 + m;
            float4 v = make_float4(0.f, 0.f, 0.f, 0.f);
            if (row < nOut)
                v = *reinterpret_cast<const float4*>(&g_M[(size_t)row * TC_DIM + kb + k4 * 4]);
            Ms[k4 * 4 + 0][m] = v.x;
            Ms[k4 * 4 + 1][m] = v.y;
            Ms[k4 * 4 + 2][m] = v.z;
            Ms[k4 * 4 + 3][m] = v.w;
        }
        // Load K tile duplicated: 16x64, one float4 per thread -> 4 dup pairs.
        {
            int k  = tid >> 4;   // 0..15
            int f4 = tid & 15;   // 0..15
            float4 v = *reinterpret_cast<const float4*>(&Kf[(size_t)(kb + k) * F_DIM + f4 * 4]);
            ull d0, d1, d2, d3;
            asm("mov.b64 %0, {%1, %1};" : "=l"(d0) : "r"(__float_as_uint(v.x)));
            asm("mov.b64 %0, {%1, %1};" : "=l"(d1) : "r"(__float_as_uint(v.y)));
            asm("mov.b64 %0, {%1, %1};" : "=l"(d2) : "r"(__float_as_uint(v.z)));
            asm("mov.b64 %0, {%1, %1};" : "=l"(d3) : "r"(__float_as_uint(v.w)));
            NsD[k][f4 * 4 + 0] = d0;
            NsD[k][f4 * 4 + 1] = d1;
            NsD[k][f4 * 4 + 2] = d2;
            NsD[k][f4 * 4 + 3] = d3;
        }
        __syncthreads();

#pragma unroll
        for (int k = 0; k < BK; k++) {
            const ulonglong2* pa = reinterpret_cast<const ulonglong2*>(&Ms[k][ty * TM]);
            ulonglong2 A0 = pa[0], A1 = pa[1];        // (m0,m1)(m2,m3)(m4,m5)(m6,m7)
            const ulonglong2* pb = reinterpret_cast<const ulonglong2*>(&NsD[k][tx * TN]);
            ulonglong2 B0 = pb[0], B1 = pb[1];        // dup b for cols j0..j3
            ull a_[4] = {A0.x, A0.y, A1.x, A1.y};
            ull b_[4] = {B0.x, B0.y, B1.x, B1.y};
#pragma unroll
            for (int p = 0; p < 4; p++)
#pragma unroll
                for (int j = 0; j < 4; j++)
                    asm("fma.rn.f32x2 %0, %1, %2, %0;" : "+l"(acc2[p][j]) : "l"(a_[p]), "l"(b_[j]));
        }
        __syncthreads();
    }

    float4 bv = *reinterpret_cast<const float4*>(&bias[tx * TN]);
    float bb[4] = {bv.x, bv.y, bv.z, bv.w};
#pragma unroll
    for (int p = 0; p < TM / 2; p++) {
#pragma unroll
        for (int h = 0; h < 2; h++) {
            int row = row0 + ty * TM + 2 * p + h;
            if (row < nOut) {
                float vals[4];
#pragma unroll
                for (int j = 0; j < 4; j++) {
                    float2 f = *reinterpret_cast<float2*>(&acc2[p][j]);
                    vals[j] = (h == 0 ? f.x : f.y) + bb[j];
                }
                *reinterpret_cast<float4*>(&out[(size_t)row * F_DIM + tx * TN]) =
                    make_float4(vals[0], vals[1], vals[2], vals[3]);
            }
        }
    }
}

// ---------------- launch ---------------------------------------------------------
extern "C" void kernel_launch(void* const* d_in, const int* in_sizes, int n_in,
                              void* d_out, int out_size) {
    const float* node = (const float*)d_in[0];
    const float* edge = (const float*)d_in[1];
    const void*  idx  = d_in[2];
    const float* kern = (const float*)d_in[3];
    const float* bias = (const float*)d_in[4];
    float* out = (float*)d_out;

    int E    = in_sizes[1] / T_DIM;   // edge_features is (T, E)
    int nOut = out_size / F_DIM;      // output is (N_OUT, F)
    int nb   = (nOut + 1023) / 1024;

    k_init<<<(nOut + 255) / 256, 256>>>(nOut, idx);
    k_hist<<<(E + 255) / 256, 256>>>(idx, E);
    k_scan1<<<nb, 1024>>>(nOut);
    k_scan2<<<1, 64>>>(nb);
    k_scan3<<<nb, 1024>>>(nOut, E);
    k_fill<<<(E + 255) / 256, 256>>>(idx, edge, E);
    k_accum<<<(nOut + 3) / 4, 256>>>(node, nOut);
    k_gemm<<<(nOut + BM - 1) / BM, 256>>>(kern, bias, out, nOut);
}

// round 4
// speedup vs baseline: 1.4248x; 1.4248x over previous
#include <cuda_runtime.h>
#include <cuda_bf16.h>
#include <cstdint>

// Problem constants: C=64 in-channels, T=8 terms, F=64 out.
#define C_DIM 64
#define T_DIM 8
#define F_DIM 64
#define TC_DIM 512  // T*C

#define EMAX 800000
#define NOUTMAX 50176  // 50000 rounded up to multiple of 128

typedef unsigned long long ull;
typedef unsigned int uint;

// ---------------- scratch (__device__ globals; no allocations allowed) ----------
__device__ int   g_is64;
__device__ int   g_count[NOUTMAX];
__device__ ull   g_state[64];                 // decoupled-lookback scan state
__device__ int   g_offsets[NOUTMAX + 1];
__device__ int   g_cursor[NOUTMAX];
__device__ int   g_src[EMAX];                 // idx_in per CSR slot
__device__ float g_edgeW[(size_t)EMAX * T_DIM];
// M and K^T in bf16 hi/lo, K-dim permuted for mma fragment loads.
// Zero-init pad rows (never written) are +0.0bf16 -> safe for mma.
__device__ unsigned short g_Mh[(size_t)NOUTMAX * TC_DIM];
__device__ unsigned short g_Ml[(size_t)NOUTMAX * TC_DIM];
__device__ unsigned short g_Kh[F_DIM * TC_DIM];   // [n][k'] = Kf[k][n]
__device__ unsigned short g_Kl[F_DIM * TC_DIM];

// K-dim permutation: within each 16-element group, reorder so lane (t=k-pair idx)
// finds its 4 fragment elements {2t,2t+1,2t+8,2t+9} contiguous at offset t*4.
__device__ __forceinline__ int permk(int k) {
    return (k & ~15) | (((k >> 1) & 3) << 2) | (((k >> 3) & 1) << 1) | (k & 1);
}

// ---------------- index dtype helper --------------------------------------------
__device__ __forceinline__ int idx_at(const void* p, long long i) {
    if (g_is64) return (int)((const long long*)p)[i];
    return ((const int*)p)[i];
}

__device__ __forceinline__ void split_store(unsigned short* hi, unsigned short* lo,
                                            size_t idx, float v) {
    __nv_bfloat16 h = __float2bfloat16(v);
    float hf = __bfloat162float(h);
    __nv_bfloat16 l = __float2bfloat16(v - hf);
    hi[idx] = __bfloat16_as_ushort(h);
    lo[idx] = __bfloat16_as_ushort(l);
}

// ---------------- init: zero counters/state + prep K + detect index dtype --------
__global__ void k_init(int nOut, const void* idx, const float* __restrict__ Kf) {
    int i = blockIdx.x * blockDim.x + threadIdx.x;
    if (i < nOut) g_count[i] = 0;
    if (i < 64) g_state[i] = 0ull;
    if (i < TC_DIM * F_DIM) {
        int k = i >> 6, n = i & 63;
        split_store(g_Kh, g_Kl, (size_t)n * TC_DIM + permk(k), Kf[i]);
    }
    if (i == 0) {
        // int64 (nonneg < 2^31): every odd 32-bit word is zero.
        const unsigned* w = (const unsigned*)idx;
        int is64 = 1;
        for (int j = 0; j < 64; j++) {
            if (w[2 * j + 1] != 0u) { is64 = 0; break; }
        }
        g_is64 = is64;
    }
}

__global__ void k_hist(const void* idx, int E) {
    int e = blockIdx.x * blockDim.x + threadIdx.x;
    if (e < E) {
        int o = idx_at(idx, 2LL * e);
        atomicAdd(&g_count[o], 1);
    }
}

// ---------------- single-pass scan with decoupled lookback -----------------------
#define FLAG_AGG (1ull << 32)
#define FLAG_PFX (2ull << 32)

__global__ void k_scan(int nOut, int E) {
    __shared__ int wsum[32];
    __shared__ int sh_total;
    __shared__ int sh_excl;
    int tid = threadIdx.x;
    int lane = tid & 31, wid = tid >> 5;
    int b = blockIdx.x;
    int i = b * 1024 + tid;
    int v = (i < nOut) ? g_count[i] : 0;

    int s = v;
#pragma unroll
    for (int off = 1; off < 32; off <<= 1) {
        int t = __shfl_up_sync(0xffffffffu, s, off);
        if (lane >= off) s += t;
    }
    if (lane == 31) wsum[wid] = s;
    __syncthreads();
    if (wid == 0) {
        int ws = wsum[lane];
#pragma unroll
        for (int off = 1; off < 32; off <<= 1) {
            int t = __shfl_up_sync(0xffffffffu, ws, off);
            if (lane >= off) ws += t;
        }
        wsum[lane] = ws;
    }
    __syncthreads();
    int incl = s + (wid > 0 ? wsum[wid - 1] : 0);
    if (tid == 1023) sh_total = incl;
    __syncthreads();

    if (tid == 0) {
        int total = sh_total;
        if (b == 0) {
            atomicExch(&g_state[0], FLAG_PFX | (unsigned)total);
            sh_excl = 0;
        } else {
            atomicExch(&g_state[b], FLAG_AGG | (unsigned)total);
            int run = 0;
            for (int j = b - 1; j >= 0;) {
                ull st;
                do { st = atomicAdd(&g_state[j], 0ull); } while ((st >> 32) == 0ull);
                run += (int)(unsigned)st;
                if ((st >> 32) == 2ull) break;
                j--;
            }
            atomicExch(&g_state[b], FLAG_PFX | (unsigned)(run + total));
            sh_excl = run;
        }
    }
    __syncthreads();

    int excl = sh_excl + incl - v;
    if (i < nOut) { g_offsets[i] = excl; g_cursor[i] = excl; }
    if (b == 0 && tid == 0) g_offsets[nOut] = E;
}

// Fill CSR: also pre-gather per-edge weight vector (transposed to (slot, T)).
__global__ void k_fill(const void* idx, const float* __restrict__ edge, int E) {
    int e = blockIdx.x * blockDim.x + threadIdx.x;
    if (e >= E) return;
    int o  = idx_at(idx, 2LL * e);
    int in = idx_at(idx, 2LL * e + 1);
    int p = atomicAdd(&g_cursor[o], 1);
    g_src[p] = in;
    float w[T_DIM];
#pragma unroll
    for (int t = 0; t < T_DIM; t++) w[t] = edge[(size_t)t * E + e];
    float4* dst = reinterpret_cast<float4*>(g_edgeW + (size_t)p * 8);
    dst[0] = make_float4(w[0], w[1], w[2], w[3]);
    dst[1] = make_float4(w[4], w[5], w[6], w[7]);
}

// ---------------- edge accumulation: M[o, t*64+c] (R1 scalar loop) ---------------
__global__ void k_accum(const float* __restrict__ node, int nOut) {
    int tid = threadIdx.x;
    int c = tid & 63;
    int o = blockIdx.x * 4 + (tid >> 6);
    if (o >= nOut) return;

    int beg = g_offsets[o];
    int end = g_offsets[o + 1];

    float s0 = 0.f, s1 = 0.f, s2 = 0.f, s3 = 0.f;
    float s4 = 0.f, s5 = 0.f, s6 = 0.f, s7 = 0.f;

#pragma unroll 2
    for (int i = beg; i < end; i++) {
        int in = g_src[i];
        float4 wa = *reinterpret_cast<const float4*>(g_edgeW + (size_t)i * 8);
        float4 wb = *reinterpret_cast<const float4*>(g_edgeW + (size_t)i * 8 + 4);
        float nv = node[(size_t)in * C_DIM + c];
        s0 += wa.x * nv; s1 += wa.y * nv; s2 += wa.z * nv; s3 += wa.w * nv;
        s4 += wb.x * nv; s5 += wb.y * nv; s6 += wb.z * nv; s7 += wb.w * nv;
    }

    int pc = permk(c);  // permuted within-64 channel position
    size_t base = (size_t)o * TC_DIM + pc;
    split_store(g_Mh, g_Ml, base + 0 * 64, s0);
    split_store(g_Mh, g_Ml, base + 1 * 64, s1);
    split_store(g_Mh, g_Ml, base + 2 * 64, s2);
    split_store(g_Mh, g_Ml, base + 3 * 64, s3);
    split_store(g_Mh, g_Ml, base + 4 * 64, s4);
    split_store(g_Mh, g_Ml, base + 5 * 64, s5);
    split_store(g_Mh, g_Ml, base + 6 * 64, s6);
    split_store(g_Mh, g_Ml, base + 7 * 64, s7);
}

// ---------------- GEMM via warp-level mma.sync (bf16 x3 products) ----------------
__device__ __forceinline__ void mma16816(float* d, uint a0, uint a1, uint a2, uint a3,
                                         uint b0, uint b1) {
    asm volatile(
        "mma.sync.aligned.m16n8k16.row.col.f32.bf16.bf16.f32 "
        "{%0,%1,%2,%3}, {%4,%5,%6,%7}, {%8,%9}, {%0,%1,%2,%3};"
        : "+f"(d[0]), "+f"(d[1]), "+f"(d[2]), "+f"(d[3])
        : "r"(a0), "r"(a1), "r"(a2), "r"(a3), "r"(b0), "r"(b1));
}

__global__ __launch_bounds__(128) void k_gemm(const float* __restrict__ bias,
                                              float* __restrict__ out, int nOut) {
    int tid = threadIdx.x, w = tid >> 5, lane = tid & 31;
    int g = lane >> 2, t = lane & 3;
    int rowbase = blockIdx.x * 128 + w * 32;

    size_t abase = (size_t)(rowbase + g) * TC_DIM + t * 4;
    size_t bbase = (size_t)g * TC_DIM + t * 4;

    float d[2][8][4];
#pragma unroll
    for (int mt = 0; mt < 2; mt++)
#pragma unroll
        for (int nt = 0; nt < 8; nt++)
#pragma unroll
            for (int r = 0; r < 4; r++) d[mt][nt][r] = 0.f;

#pragma unroll
    for (int p = 0; p < 3; p++) {
        const unsigned short* Ap = (p == 2) ? g_Ml : g_Mh;
        const unsigned short* Bp = (p == 1) ? g_Kl : g_Kh;
#pragma unroll 2
        for (int k0 = 0; k0 < TC_DIM; k0 += 16) {
            ull A00 = *reinterpret_cast<const ull*>(Ap + abase + k0);
            ull A01 = *reinterpret_cast<const ull*>(Ap + abase + 8 * TC_DIM + k0);
            ull A10 = *reinterpret_cast<const ull*>(Ap + abase + 16 * TC_DIM + k0);
            ull A11 = *reinterpret_cast<const ull*>(Ap + abase + 24 * TC_DIM + k0);
#pragma unroll
            for (int nt = 0; nt < 8; nt++) {
                ull Bv = *reinterpret_cast<const ull*>(Bp + bbase + nt * 8 * TC_DIM + k0);
                uint b0 = (uint)Bv, b1 = (uint)(Bv >> 32);
                mma16816(d[0][nt], (uint)A00, (uint)A01,
                         (uint)(A00 >> 32), (uint)(A01 >> 32), b0, b1);
                mma16816(d[1][nt], (uint)A10, (uint)A11,
                         (uint)(A10 >> 32), (uint)(A11 >> 32), b0, b1);
            }
        }
    }

    // Epilogue: d0=(g,2t) d1=(g,2t+1) d2=(g+8,2t) d3=(g+8,2t+1) per 16x8 tile.
#pragma unroll
    for (int mt = 0; mt < 2; mt++) {
#pragma unroll
        for (int nt = 0; nt < 8; nt++) {
            int col = nt * 8 + t * 2;
            float2 bv = *reinterpret_cast<const float2*>(bias + col);
            int r0 = rowbase + mt * 16 + g;
            if (r0 < nOut) {
                *reinterpret_cast<float2*>(&out[(size_t)r0 * F_DIM + col]) =
                    make_float2(d[mt][nt][0] + bv.x, d[mt][nt][1] + bv.y);
            }
            int r1 = r0 + 8;
            if (r1 < nOut) {
                *reinterpret_cast<float2*>(&out[(size_t)r1 * F_DIM + col]) =
                    make_float2(d[mt][nt][2] + bv.x, d[mt][nt][3] + bv.y);
            }
        }
    }
}

// ---------------- launch ---------------------------------------------------------
extern "C" void kernel_launch(void* const* d_in, const int* in_sizes, int n_in,
                              void* d_out, int out_size) {
    const float* node = (const float*)d_in[0];
    const float* edge = (const float*)d_in[1];
    const void*  idx  = d_in[2];
    const float* kern = (const float*)d_in[3];
    const float* bias = (const float*)d_in[4];
    float* out = (float*)d_out;

    int E    = in_sizes[1] / T_DIM;   // edge_features is (T, E)
    int nOut = out_size / F_DIM;      // output is (N_OUT, F)
    int nb   = (nOut + 1023) / 1024;  // <= 64

    k_init<<<(nOut + 255) / 256, 256>>>(nOut, idx, kern);
    k_hist<<<(E + 255) / 256, 256>>>(idx, E);
    k_scan<<<nb, 1024>>>(nOut, E);
    k_fill<<<(E + 255) / 256, 256>>>(idx, edge, E);
    k_accum<<<(nOut + 3) / 4, 256>>>(node, nOut);
    k_gemm<<<(nOut + 127) / 128, 128>>>(bias, out, nOut);
}

// round 5
// speedup vs baseline: 1.7561x; 1.2326x over previous
#include <cuda_runtime.h>
#include <cuda_bf16.h>
#include <cstdint>

// Problem constants: C=64 in-channels, T=8 terms, F=64 out.
#define C_DIM 64
#define T_DIM 8
#define F_DIM 64
#define TC_DIM 512  // T*C

#define EMAX 800000
#define NOUTMAX 50176  // 50000 rounded up to multiple of 128

typedef unsigned long long ull;
typedef unsigned int uint;

// ---------------- scratch (__device__ globals; no allocations allowed) ----------
__device__ int   g_is64;
__device__ int   g_count[NOUTMAX];
__device__ ull   g_state[64];                 // decoupled-lookback scan state
__device__ int   g_offsets[NOUTMAX + 1];
__device__ int   g_cursor[NOUTMAX];
__device__ int   g_src[EMAX];                 // idx_in per CSR slot
__device__ float g_edgeW[(size_t)EMAX * T_DIM];
// Packed bf16 hi/lo planes: low16 = hi(bf16 of v), high16 = lo(bf16 of v-hi).
// K-dim permuted for mma fragment loads. Zero-init pad rows = +0.0bf16, safe.
__device__ uint g_Mp[(size_t)NOUTMAX * TC_DIM];
__device__ uint g_Kp[F_DIM * TC_DIM];         // [n][k'] = pack(Kf[k][n])

// K-dim permutation: within each 16-element group, reorder so lane (t=k-pair idx)
// finds its 4 fragment elements {2t,2t+1,2t+8,2t+9} contiguous at offset t*4.
__device__ __forceinline__ int permk(int k) {
    return (k & ~15) | (((k >> 1) & 3) << 2) | (((k >> 3) & 1) << 1) | (k & 1);
}

// ---------------- index dtype helper --------------------------------------------
__device__ __forceinline__ int idx_at(const void* p, long long i) {
    if (g_is64) return (int)((const long long*)p)[i];
    return ((const int*)p)[i];
}

__device__ __forceinline__ uint split_pack(float v) {
    __nv_bfloat16 h = __float2bfloat16(v);
    float hf = __bfloat162float(h);
    __nv_bfloat16 l = __float2bfloat16(v - hf);
    return (uint)__bfloat16_as_ushort(h) | ((uint)__bfloat16_as_ushort(l) << 16);
}

// ---------------- init: zero counters/state + prep K + detect index dtype --------
__global__ void k_init(int nOut, const void* idx, const float* __restrict__ Kf) {
    int i = blockIdx.x * blockDim.x + threadIdx.x;
    if (i < nOut) g_count[i] = 0;
    if (i < 64) g_state[i] = 0ull;
    if (i < TC_DIM * F_DIM) {
        int k = i >> 6, n = i & 63;
        g_Kp[(size_t)n * TC_DIM + permk(k)] = split_pack(Kf[i]);
    }
    if (i == 0) {
        // int64 (nonneg < 2^31): every odd 32-bit word is zero.
        const unsigned* w = (const unsigned*)idx;
        int is64 = 1;
        for (int j = 0; j < 64; j++) {
            if (w[2 * j + 1] != 0u) { is64 = 0; break; }
        }
        g_is64 = is64;
    }
}

__global__ void k_hist(const void* idx, int E) {
    int e = blockIdx.x * blockDim.x + threadIdx.x;
    if (e < E) {
        int o = idx_at(idx, 2LL * e);
        atomicAdd(&g_count[o], 1);
    }
}

// ---------------- single-pass scan with decoupled lookback -----------------------
#define FLAG_AGG (1ull << 32)
#define FLAG_PFX (2ull << 32)

__global__ void k_scan(int nOut, int E) {
    __shared__ int wsum[32];
    __shared__ int sh_total;
    __shared__ int sh_excl;
    int tid = threadIdx.x;
    int lane = tid & 31, wid = tid >> 5;
    int b = blockIdx.x;
    int i = b * 1024 + tid;
    int v = (i < nOut) ? g_count[i] : 0;

    int s = v;
#pragma unroll
    for (int off = 1; off < 32; off <<= 1) {
        int t = __shfl_up_sync(0xffffffffu, s, off);
        if (lane >= off) s += t;
    }
    if (lane == 31) wsum[wid] = s;
    __syncthreads();
    if (wid == 0) {
        int ws = wsum[lane];
#pragma unroll
        for (int off = 1; off < 32; off <<= 1) {
            int t = __shfl_up_sync(0xffffffffu, ws, off);
            if (lane >= off) ws += t;
        }
        wsum[lane] = ws;
    }
    __syncthreads();
    int incl = s + (wid > 0 ? wsum[wid - 1] : 0);
    if (tid == 1023) sh_total = incl;
    __syncthreads();

    if (tid == 0) {
        int total = sh_total;
        if (b == 0) {
            atomicExch(&g_state[0], FLAG_PFX | (unsigned)total);
            sh_excl = 0;
        } else {
            atomicExch(&g_state[b], FLAG_AGG | (unsigned)total);
            int run = 0;
            for (int j = b - 1; j >= 0;) {
                ull st;
                do { st = atomicAdd(&g_state[j], 0ull); } while ((st >> 32) == 0ull);
                run += (int)(unsigned)st;
                if ((st >> 32) == 2ull) break;
                j--;
            }
            atomicExch(&g_state[b], FLAG_PFX | (unsigned)(run + total));
            sh_excl = run;
        }
    }
    __syncthreads();

    int excl = sh_excl + incl - v;
    if (i < nOut) { g_offsets[i] = excl; g_cursor[i] = excl; }
    if (b == 0 && tid == 0) g_offsets[nOut] = E;
}

// Fill CSR: also pre-gather per-edge weight vector (transposed to (slot, T)).
__global__ void k_fill(const void* idx, const float* __restrict__ edge, int E) {
    int e = blockIdx.x * blockDim.x + threadIdx.x;
    if (e >= E) return;
    int o  = idx_at(idx, 2LL * e);
    int in = idx_at(idx, 2LL * e + 1);
    int p = atomicAdd(&g_cursor[o], 1);
    g_src[p] = in;
    float w[T_DIM];
#pragma unroll
    for (int t = 0; t < T_DIM; t++) w[t] = edge[(size_t)t * E + e];
    float4* dst = reinterpret_cast<float4*>(g_edgeW + (size_t)p * 8);
    dst[0] = make_float4(w[0], w[1], w[2], w[3]);
    dst[1] = make_float4(w[4], w[5], w[6], w[7]);
}

// ---------------- edge accumulation: M[o, t*64+c] --------------------------------
__global__ void k_accum(const float* __restrict__ node, int nOut) {
    int tid = threadIdx.x;
    int c = tid & 63;
    int o = blockIdx.x * 4 + (tid >> 6);
    if (o >= nOut) return;

    int beg = g_offsets[o];
    int end = g_offsets[o + 1];

    float s0 = 0.f, s1 = 0.f, s2 = 0.f, s3 = 0.f;
    float s4 = 0.f, s5 = 0.f, s6 = 0.f, s7 = 0.f;

#pragma unroll 2
    for (int i = beg; i < end; i++) {
        int in = g_src[i];
        float4 wa = *reinterpret_cast<const float4*>(g_edgeW + (size_t)i * 8);
        float4 wb = *reinterpret_cast<const float4*>(g_edgeW + (size_t)i * 8 + 4);
        float nv = node[(size_t)in * C_DIM + c];
        s0 += wa.x * nv; s1 += wa.y * nv; s2 += wa.z * nv; s3 += wa.w * nv;
        s4 += wb.x * nv; s5 += wb.y * nv; s6 += wb.z * nv; s7 += wb.w * nv;
    }

    int pc = permk(c);  // permuted within-64 channel position
    size_t base = (size_t)o * TC_DIM + pc;
    g_Mp[base + 0 * 64] = split_pack(s0);
    g_Mp[base + 1 * 64] = split_pack(s1);
    g_Mp[base + 2 * 64] = split_pack(s2);
    g_Mp[base + 3 * 64] = split_pack(s3);
    g_Mp[base + 4 * 64] = split_pack(s4);
    g_Mp[base + 5 * 64] = split_pack(s5);
    g_Mp[base + 6 * 64] = split_pack(s6);
    g_Mp[base + 7 * 64] = split_pack(s7);
}

// ---------------- GEMM via warp-level mma.sync (bf16 x3 products) ----------------
__device__ __forceinline__ void mma16816(float* d, uint a0, uint a1, uint a2, uint a3,
                                         uint b0, uint b1) {
    asm volatile(
        "mma.sync.aligned.m16n8k16.row.col.f32.bf16.bf16.f32 "
        "{%0,%1,%2,%3}, {%4,%5,%6,%7}, {%8,%9}, {%0,%1,%2,%3};"
        : "+f"(d[0]), "+f"(d[1]), "+f"(d[2]), "+f"(d[3])
        : "r"(a0), "r"(a1), "r"(a2), "r"(a3), "r"(b0), "r"(b1));
}

__device__ __forceinline__ uint prmt(uint a, uint b, uint sel) {
    uint r;
    asm("prmt.b32 %0, %1, %2, %3;" : "=r"(r) : "r"(a), "r"(b), "r"(sel));
    return r;
}

__global__ __launch_bounds__(128) void k_gemm(const float* __restrict__ bias,
                                              float* __restrict__ out, int nOut) {
    int tid = threadIdx.x, w = tid >> 5, lane = tid & 31;
    int g = lane >> 2, t = lane & 3;
    int rowbase = blockIdx.x * 128 + w * 32;

    size_t abase = (size_t)(rowbase + g) * TC_DIM + t * 4;
    size_t bbase = (size_t)g * TC_DIM + t * 4;

    float d[2][8][4];
#pragma unroll
    for (int mt = 0; mt < 2; mt++)
#pragma unroll
        for (int nt = 0; nt < 8; nt++)
#pragma unroll
            for (int r = 0; r < 4; r++) d[mt][nt][r] = 0.f;

#pragma unroll 1
    for (int k0 = 0; k0 < TC_DIM; k0 += 16) {
        // A: 4 row-groups (g, g+8, g+16, g+24), one uint4 each = 4 packed k-elems.
        uint4 q0 = *reinterpret_cast<const uint4*>(g_Mp + abase + k0);
        uint4 q1 = *reinterpret_cast<const uint4*>(g_Mp + abase + 8 * TC_DIM + k0);
        uint4 q2 = *reinterpret_cast<const uint4*>(g_Mp + abase + 16 * TC_DIM + k0);
        uint4 q3 = *reinterpret_cast<const uint4*>(g_Mp + abase + 24 * TC_DIM + k0);
        // hi plane fragments (a0,a1 per row-group)
        uint h00 = prmt(q0.x, q0.y, 0x5410), h01 = prmt(q0.z, q0.w, 0x5410);
        uint h10 = prmt(q1.x, q1.y, 0x5410), h11 = prmt(q1.z, q1.w, 0x5410);
        uint h20 = prmt(q2.x, q2.y, 0x5410), h21 = prmt(q2.z, q2.w, 0x5410);
        uint h30 = prmt(q3.x, q3.y, 0x5410), h31 = prmt(q3.z, q3.w, 0x5410);
        // lo plane fragments
        uint l00 = prmt(q0.x, q0.y, 0x7632), l01 = prmt(q0.z, q0.w, 0x7632);
        uint l10 = prmt(q1.x, q1.y, 0x7632), l11 = prmt(q1.z, q1.w, 0x7632);
        uint l20 = prmt(q2.x, q2.y, 0x7632), l21 = prmt(q2.z, q2.w, 0x7632);
        uint l30 = prmt(q3.x, q3.y, 0x7632), l31 = prmt(q3.z, q3.w, 0x7632);

#pragma unroll
        for (int nt = 0; nt < 8; nt++) {
            uint4 qb = *reinterpret_cast<const uint4*>(g_Kp + bbase + (size_t)nt * 8 * TC_DIM + k0);
            uint bh0 = prmt(qb.x, qb.y, 0x5410), bh1 = prmt(qb.z, qb.w, 0x5410);
            uint bl0 = prmt(qb.x, qb.y, 0x7632), bl1 = prmt(qb.z, qb.w, 0x7632);
            // d += Mh*Kh + Mh*Kl + Ml*Kh  (all into same accumulators)
            mma16816(d[0][nt], h00, h10, h01, h11, bh0, bh1);
            mma16816(d[0][nt], h00, h10, h01, h11, bl0, bl1);
            mma16816(d[0][nt], l00, l10, l01, l11, bh0, bh1);
            mma16816(d[1][nt], h20, h30, h21, h31, bh0, bh1);
            mma16816(d[1][nt], h20, h30, h21, h31, bl0, bl1);
            mma16816(d[1][nt], l20, l30, l21, l31, bh0, bh1);
        }
    }

    // Epilogue: d0=(g,2t) d1=(g,2t+1) d2=(g+8,2t) d3=(g+8,2t+1) per 16x8 tile.
#pragma unroll
    for (int mt = 0; mt < 2; mt++) {
#pragma unroll
        for (int nt = 0; nt < 8; nt++) {
            int col = nt * 8 + t * 2;
            float2 bv = *reinterpret_cast<const float2*>(bias + col);
            int r0 = rowbase + mt * 16 + g;
            if (r0 < nOut) {
                *reinterpret_cast<float2*>(&out[(size_t)r0 * F_DIM + col]) =
                    make_float2(d[mt][nt][0] + bv.x, d[mt][nt][1] + bv.y);
            }
            int r1 = r0 + 8;
            if (r1 < nOut) {
                *reinterpret_cast<float2*>(&out[(size_t)r1 * F_DIM + col]) =
                    make_float2(d[mt][nt][2] + bv.x, d[mt][nt][3] + bv.y);
            }
        }
    }
}

// ---------------- launch ---------------------------------------------------------
extern "C" void kernel_launch(void* const* d_in, const int* in_sizes, int n_in,
                              void* d_out, int out_size) {
    const float* node = (const float*)d_in[0];
    const float* edge = (const float*)d_in[1];
    const void*  idx  = d_in[2];
    const float* kern = (const float*)d_in[3];
    const float* bias = (const float*)d_in[4];
    float* out = (float*)d_out;

    int E    = in_sizes[1] / T_DIM;   // edge_features is (T, E)
    int nOut = out_size / F_DIM;      // output is (N_OUT, F)
    int nb   = (nOut + 1023) / 1024;  // <= 64

    k_init<<<(nOut + 255) / 256, 256>>>(nOut, idx, kern);
    k_hist<<<(E + 255) / 256, 256>>>(idx, E);
    k_scan<<<nb, 1024>>>(nOut, E);
    k_fill<<<(E + 255) / 256, 256>>>(idx, edge, E);
    k_accum<<<(nOut + 3) / 4, 256>>>(node, nOut);
    k_gemm<<<(nOut + 127) / 128, 128>>>(bias, out, nOut);
}

// round 6
// speedup vs baseline: 1.9071x; 1.0860x over previous
#include <cuda_runtime.h>
#include <cuda_bf16.h>
#include <cstdint>

// Problem constants: C=64 in-channels, T=8 terms, F=64 out.
#define C_DIM 64
#define T_DIM 8
#define F_DIM 64
#define TC_DIM 512  // T*C

#define EMAX 800000
#define NOUTMAX 50176  // 50000 rounded up to multiple of 128

typedef unsigned long long ull;
typedef unsigned int uint;

// ---------------- scratch (__device__ globals; no allocations allowed) ----------
__device__ int   g_is64;
__device__ int   g_count[NOUTMAX];
__device__ ull   g_state[64];                 // decoupled-lookback scan state
__device__ int   g_offsets[NOUTMAX + 1];
__device__ int   g_rank[EMAX];                // per-edge rank within its output bin
__device__ int   g_src[EMAX];                 // idx_in per CSR slot
__device__ float g_edgeW[(size_t)EMAX * T_DIM];
// Packed bf16 hi/lo planes: low16 = hi(bf16 of v), high16 = lo(bf16 of v-hi).
// K-dim permuted for mma fragment loads. Zero-init pad rows = +0.0bf16, safe.
__device__ uint g_Mp[(size_t)NOUTMAX * TC_DIM];
__device__ uint g_Kp[F_DIM * TC_DIM];         // [n][k'] = pack(Kf[k][n])

// K-dim permutation: within each 16-element group, reorder so lane (t=k-pair idx)
// finds its 4 fragment elements {2t,2t+1,2t+8,2t+9} contiguous at offset t*4.
// Note: preserves bit0, so channel pairs (2j, 2j+1) stay adjacent.
__device__ __forceinline__ int permk(int k) {
    return (k & ~15) | (((k >> 1) & 3) << 2) | (((k >> 3) & 1) << 1) | (k & 1);
}

// ---------------- index dtype helper --------------------------------------------
__device__ __forceinline__ int idx_at(const void* p, long long i) {
    if (g_is64) return (int)((const long long*)p)[i];
    return ((const int*)p)[i];
}

__device__ __forceinline__ uint split_pack(float v) {
    __nv_bfloat16 h = __float2bfloat16(v);
    float hf = __bfloat162float(h);
    __nv_bfloat16 l = __float2bfloat16(v - hf);
    return (uint)__bfloat16_as_ushort(h) | ((uint)__bfloat16_as_ushort(l) << 16);
}

// ---------------- init: zero counters/state + prep K + detect index dtype --------
__global__ void k_init(int nOut, const void* idx, const float* __restrict__ Kf) {
    int i = blockIdx.x * blockDim.x + threadIdx.x;
    if (i < nOut) g_count[i] = 0;
    if (i < 64) g_state[i] = 0ull;
    if (i < TC_DIM * F_DIM) {
        int k = i >> 6, n = i & 63;
        g_Kp[(size_t)n * TC_DIM + permk(k)] = split_pack(Kf[i]);
    }
    if (i == 0) {
        // int64 (nonneg < 2^31): every odd 32-bit word is zero.
        const unsigned* w = (const unsigned*)idx;
        int is64 = 1;
        for (int j = 0; j < 64; j++) {
            if (w[2 * j + 1] != 0u) { is64 = 0; break; }
        }
        g_is64 = is64;
    }
}

// Histogram; the atomic's return value is the edge's rank within its bin.
__global__ void k_hist(const void* idx, int E) {
    int e = blockIdx.x * blockDim.x + threadIdx.x;
    if (e < E) {
        int o = idx_at(idx, 2LL * e);
        g_rank[e] = atomicAdd(&g_count[o], 1);
    }
}

// ---------------- single-pass scan with decoupled lookback -----------------------
#define FLAG_AGG (1ull << 32)
#define FLAG_PFX (2ull << 32)

__global__ void k_scan(int nOut, int E) {
    __shared__ int wsum[32];
    __shared__ int sh_total;
    __shared__ int sh_excl;
    int tid = threadIdx.x;
    int lane = tid & 31, wid = tid >> 5;
    int b = blockIdx.x;
    int i = b * 1024 + tid;
    int v = (i < nOut) ? g_count[i] : 0;

    int s = v;
#pragma unroll
    for (int off = 1; off < 32; off <<= 1) {
        int t = __shfl_up_sync(0xffffffffu, s, off);
        if (lane >= off) s += t;
    }
    if (lane == 31) wsum[wid] = s;
    __syncthreads();
    if (wid == 0) {
        int ws = wsum[lane];
#pragma unroll
        for (int off = 1; off < 32; off <<= 1) {
            int t = __shfl_up_sync(0xffffffffu, ws, off);
            if (lane >= off) ws += t;
        }
        wsum[lane] = ws;
    }
    __syncthreads();
    int incl = s + (wid > 0 ? wsum[wid - 1] : 0);
    if (tid == 1023) sh_total = incl;
    __syncthreads();

    if (tid == 0) {
        int total = sh_total;
        if (b == 0) {
            atomicExch(&g_state[0], FLAG_PFX | (unsigned)total);
            sh_excl = 0;
        } else {
            atomicExch(&g_state[b], FLAG_AGG | (unsigned)total);
            int run = 0;
            for (int j = b - 1; j >= 0;) {
                ull st;
                do { st = atomicAdd(&g_state[j], 0ull); } while ((st >> 32) == 0ull);
                run += (int)(unsigned)st;
                if ((st >> 32) == 2ull) break;
                j--;
            }
            atomicExch(&g_state[b], FLAG_PFX | (unsigned)(run + total));
            sh_excl = run;
        }
    }
    __syncthreads();

    int excl = sh_excl + incl - v;
    if (i < nOut) g_offsets[i] = excl;
    if (b == 0 && tid == 0) g_offsets[nOut] = E;
}

// Fill CSR (atomic-free): p = offsets[o] + rank[e]. Pre-gathers edge weights
// transposed to (slot, T).
__global__ void k_fill(const void* idx, const float* __restrict__ edge, int E) {
    int e = blockIdx.x * blockDim.x + threadIdx.x;
    if (e >= E) return;
    int o  = idx_at(idx, 2LL * e);
    int in = idx_at(idx, 2LL * e + 1);
    int p = g_offsets[o] + g_rank[e];
    g_src[p] = in;
    float w[T_DIM];
#pragma unroll
    for (int t = 0; t < T_DIM; t++) w[t] = edge[(size_t)t * E + e];
    float4* dst = reinterpret_cast<float4*>(g_edgeW + (size_t)p * 8);
    dst[0] = make_float4(w[0], w[1], w[2], w[3]);
    dst[1] = make_float4(w[4], w[5], w[6], w[7]);
}

// ---------------- edge accumulation: M[o, t*64+c] --------------------------------
// One warp per output; each lane owns channels (2*lane, 2*lane+1).
__global__ void k_accum(const float* __restrict__ node, int nOut) {
    int warp = (blockIdx.x * blockDim.x + threadIdx.x) >> 5;
    int lane = threadIdx.x & 31;
    if (warp >= nOut) return;
    int o = warp;

    int beg = g_offsets[o];
    int end = g_offsets[o + 1];

    float sx[T_DIM], sy[T_DIM];
#pragma unroll
    for (int t = 0; t < T_DIM; t++) { sx[t] = 0.f; sy[t] = 0.f; }

#pragma unroll 2
    for (int i = beg; i < end; i++) {
        int in = g_src[i];
        float4 wa = *reinterpret_cast<const float4*>(g_edgeW + (size_t)i * 8);
        float4 wb = *reinterpret_cast<const float4*>(g_edgeW + (size_t)i * 8 + 4);
        float2 nv = *reinterpret_cast<const float2*>(&node[(size_t)in * C_DIM + lane * 2]);
        sx[0] += wa.x * nv.x; sy[0] += wa.x * nv.y;
        sx[1] += wa.y * nv.x; sy[1] += wa.y * nv.y;
        sx[2] += wa.z * nv.x; sy[2] += wa.z * nv.y;
        sx[3] += wa.w * nv.x; sy[3] += wa.w * nv.y;
        sx[4] += wb.x * nv.x; sy[4] += wb.x * nv.y;
        sx[5] += wb.y * nv.x; sy[5] += wb.y * nv.y;
        sx[6] += wb.z * nv.x; sy[6] += wb.z * nv.y;
        sx[7] += wb.w * nv.x; sy[7] += wb.w * nv.y;
    }

    int pc = permk(lane * 2);  // even; pair (pc, pc+1) is this lane's channel pair
    size_t base = (size_t)o * TC_DIM + pc;
#pragma unroll
    for (int t = 0; t < T_DIM; t++) {
        *reinterpret_cast<uint2*>(&g_Mp[base + (size_t)t * 64]) =
            make_uint2(split_pack(sx[t]), split_pack(sy[t]));
    }
}

// ---------------- GEMM via warp-level mma.sync (bf16 x3 products) ----------------
__device__ __forceinline__ void mma16816(float* d, uint a0, uint a1, uint a2, uint a3,
                                         uint b0, uint b1) {
    asm volatile(
        "mma.sync.aligned.m16n8k16.row.col.f32.bf16.bf16.f32 "
        "{%0,%1,%2,%3}, {%4,%5,%6,%7}, {%8,%9}, {%0,%1,%2,%3};"
        : "+f"(d[0]), "+f"(d[1]), "+f"(d[2]), "+f"(d[3])
        : "r"(a0), "r"(a1), "r"(a2), "r"(a3), "r"(b0), "r"(b1));
}

__device__ __forceinline__ uint prmt(uint a, uint b, uint sel) {
    uint r;
    asm("prmt.b32 %0, %1, %2, %3;" : "=r"(r) : "r"(a), "r"(b), "r"(sel));
    return r;
}

__global__ __launch_bounds__(128) void k_gemm(const float* __restrict__ bias,
                                              float* __restrict__ out, int nOut) {
    int tid = threadIdx.x, w = tid >> 5, lane = tid & 31;
    int g = lane >> 2, t = lane & 3;
    int rowbase = blockIdx.x * 128 + w * 32;

    size_t abase = (size_t)(rowbase + g) * TC_DIM + t * 4;
    size_t bbase = (size_t)g * TC_DIM + t * 4;

    float d[2][8][4];
#pragma unroll
    for (int mt = 0; mt < 2; mt++)
#pragma unroll
        for (int nt = 0; nt < 8; nt++)
#pragma unroll
            for (int r = 0; r < 4; r++) d[mt][nt][r] = 0.f;

#pragma unroll 1
    for (int k0 = 0; k0 < TC_DIM; k0 += 16) {
        // A: 4 row-groups (g, g+8, g+16, g+24), one uint4 each = 4 packed k-elems.
        uint4 q0 = *reinterpret_cast<const uint4*>(g_Mp + abase + k0);
        uint4 q1 = *reinterpret_cast<const uint4*>(g_Mp + abase + 8 * TC_DIM + k0);
        uint4 q2 = *reinterpret_cast<const uint4*>(g_Mp + abase + 16 * TC_DIM + k0);
        uint4 q3 = *reinterpret_cast<const uint4*>(g_Mp + abase + 24 * TC_DIM + k0);
        // hi plane fragments (a0,a1 per row-group)
        uint h00 = prmt(q0.x, q0.y, 0x5410), h01 = prmt(q0.z, q0.w, 0x5410);
        uint h10 = prmt(q1.x, q1.y, 0x5410), h11 = prmt(q1.z, q1.w, 0x5410);
        uint h20 = prmt(q2.x, q2.y, 0x5410), h21 = prmt(q2.z, q2.w, 0x5410);
        uint h30 = prmt(q3.x, q3.y, 0x5410), h31 = prmt(q3.z, q3.w, 0x5410);
        // lo plane fragments
        uint l00 = prmt(q0.x, q0.y, 0x7632), l01 = prmt(q0.z, q0.w, 0x7632);
        uint l10 = prmt(q1.x, q1.y, 0x7632), l11 = prmt(q1.z, q1.w, 0x7632);
        uint l20 = prmt(q2.x, q2.y, 0x7632), l21 = prmt(q2.z, q2.w, 0x7632);
        uint l30 = prmt(q3.x, q3.y, 0x7632), l31 = prmt(q3.z, q3.w, 0x7632);

#pragma unroll
        for (int nt = 0; nt < 8; nt++) {
            uint4 qb = *reinterpret_cast<const uint4*>(g_Kp + bbase + (size_t)nt * 8 * TC_DIM + k0);
            uint bh0 = prmt(qb.x, qb.y, 0x5410), bh1 = prmt(qb.z, qb.w, 0x5410);
            uint bl0 = prmt(qb.x, qb.y, 0x7632), bl1 = prmt(qb.z, qb.w, 0x7632);
            // d += Mh*Kh + Mh*Kl + Ml*Kh  (all into same accumulators)
            mma16816(d[0][nt], h00, h10, h01, h11, bh0, bh1);
            mma16816(d[0][nt], h00, h10, h01, h11, bl0, bl1);
            mma16816(d[0][nt], l00, l10, l01, l11, bh0, bh1);
            mma16816(d[1][nt], h20, h30, h21, h31, bh0, bh1);
            mma16816(d[1][nt], h20, h30, h21, h31, bl0, bl1);
            mma16816(d[1][nt], l20, l30, l21, l31, bh0, bh1);
        }
    }

    // Epilogue: d0=(g,2t) d1=(g,2t+1) d2=(g+8,2t) d3=(g+8,2t+1) per 16x8 tile.
#pragma unroll
    for (int mt = 0; mt < 2; mt++) {
#pragma unroll
        for (int nt = 0; nt < 8; nt++) {
            int col = nt * 8 + t * 2;
            float2 bv = *reinterpret_cast<const float2*>(bias + col);
            int r0 = rowbase + mt * 16 + g;
            if (r0 < nOut) {
                *reinterpret_cast<float2*>(&out[(size_t)r0 * F_DIM + col]) =
                    make_float2(d[mt][nt][0] + bv.x, d[mt][nt][1] + bv.y);
            }
            int r1 = r0 + 8;
            if (r1 < nOut) {
                *reinterpret_cast<float2*>(&out[(size_t)r1 * F_DIM + col]) =
                    make_float2(d[mt][nt][2] + bv.x, d[mt][nt][3] + bv.y);
            }
        }
    }
}

// ---------------- launch ---------------------------------------------------------
extern "C" void kernel_launch(void* const* d_in, const int* in_sizes, int n_in,
                              void* d_out, int out_size) {
    const float* node = (const float*)d_in[0];
    const float* edge = (const float*)d_in[1];
    const void*  idx  = d_in[2];
    const float* kern = (const float*)d_in[3];
    const float* bias = (const float*)d_in[4];
    float* out = (float*)d_out;

    int E    = in_sizes[1] / T_DIM;   // edge_features is (T, E)
    int nOut = out_size / F_DIM;      // output is (N_OUT, F)
    int nb   = (nOut + 1023) / 1024;  // <= 64

    k_init<<<(nOut + 255) / 256, 256>>>(nOut, idx, kern);
    k_hist<<<(E + 255) / 256, 256>>>(idx, E);
    k_scan<<<nb, 1024>>>(nOut, E);
    k_fill<<<(E + 255) / 256, 256>>>(idx, edge, E);
    k_accum<<<(nOut * 32 + 255) / 256, 256>>>(node, nOut);
    k_gemm<<<(nOut + 127) / 128, 128>>>(bias, out, nOut);
}